// round 3
// baseline (speedup 1.0000x reference)
#include <cuda_runtime.h>
#include <cstdint>

#define B_DIM 32
#define IN_PLANES 128
#define PLANES 32

// packed f32x2 FMA: lo += x.lo*w.lo ; hi += x.hi*w.hi (full fp32 precision, 2x FFMA rate)
#define FMA2(a, xx, ww) asm("fma.rn.f32x2 %0, %1, %2, %0;" : "+l"(a) : "l"(xx), "l"(ww))

static __device__ __forceinline__ unsigned long long dal(double d) {
    return __double_as_longlong(d);
}

// xs swizzle: row b, 16B-chunk k4 lives at chunk (k4 ^ sw_x(b)) of row b.
// sw_x(b) = (b&7) ^ ((b>>3)&1): rows {i,4+i,8+i,12+i} -> 4 distinct bank quads.
static __device__ __forceinline__ int sw_x(int b) {
    return (b & 7) ^ ((b >> 3) & 1);
}

// wsT swizzle: element (o, chunk k4) at o*128 + ((k4 ^ (o&7))<<2)
static __device__ __forceinline__ int wsT_off(int o, int k4) {
    return o * IN_PLANES + (((k4) ^ (o & 7)) << 2);
}

__global__ __launch_bounds__(64) void voxel_mlp_kernel(
    const float* __restrict__ x,        // [B, n_sel, 128]
    const int*   __restrict__ vidx,     // [n_sel]
    const float* __restrict__ w0,       // [n_vox, 128, 32]
    const float* __restrict__ b0,       // [n_vox, 32]
    const float* __restrict__ w1,       // [n_vox, 32] (last dim 1)
    const float* __restrict__ b1,       // [n_vox]
    float*       __restrict__ out,      // [B, n_sel]
    int n_sel)
{
    __shared__ float xs[B_DIM * IN_PLANES];      // swizzled x rows, pitch 128
    __shared__ float wsT[PLANES * IN_PLANES];    // swizzled transposed w0

    const int n = blockIdx.x;
    const int t = threadIdx.x;
    const int v = vidx[n];

    const float* xg = x  + (size_t)n * IN_PLANES;
    const float* wg = w0 + (size_t)v * (IN_PLANES * PLANES);

    // ---- load x: coalesced LDG.128 -> swizzled STS.128 (conflict-free) ----
    #pragma unroll
    for (int m = 0; m < 16; m++) {
        int j  = t + 64 * m;
        int b  = j >> 5;        // 0..31 (warp-uniform)
        int c4 = j & 31;        // 16B chunk index = k4
        float4 val = *reinterpret_cast<const float4*>(xg + (size_t)b * n_sel * IN_PLANES + c4 * 4);
        *reinterpret_cast<float4*>(&xs[b * IN_PLANES + ((c4 ^ sw_x(b)) << 2)]) = val;
    }

    // ---- load w0 [128][32]: register 4x4-block transpose into swizzled wsT ----
    {
        const int l   = t & 31;
        const int wrp = t >> 5;
        const int o4  = l >> 2;
        #pragma unroll
        for (int it = 0; it < 4; it++) {
            const int k0 = ((l & 3) << 2) + (wrp << 4) + (it << 5);
            float4 f0 = *reinterpret_cast<const float4*>(wg + (k0 + 0) * PLANES + o4 * 4);
            float4 f1 = *reinterpret_cast<const float4*>(wg + (k0 + 1) * PLANES + o4 * 4);
            float4 f2 = *reinterpret_cast<const float4*>(wg + (k0 + 2) * PLANES + o4 * 4);
            float4 f3 = *reinterpret_cast<const float4*>(wg + (k0 + 3) * PLANES + o4 * 4);
            const int k4 = k0 >> 2;
            float4 t0 = make_float4(f0.x, f1.x, f2.x, f3.x);
            float4 t1 = make_float4(f0.y, f1.y, f2.y, f3.y);
            float4 t2 = make_float4(f0.z, f1.z, f2.z, f3.z);
            float4 t3 = make_float4(f0.w, f1.w, f2.w, f3.w);
            *reinterpret_cast<float4*>(&wsT[wsT_off(4 * o4 + 0, k4)]) = t0;
            *reinterpret_cast<float4*>(&wsT[wsT_off(4 * o4 + 1, k4)]) = t1;
            *reinterpret_cast<float4*>(&wsT[wsT_off(4 * o4 + 2, k4)]) = t2;
            *reinterpret_cast<float4*>(&wsT[wsT_off(4 * o4 + 3, k4)]) = t3;
        }
    }
    __syncthreads();

    // thread tile: b in {4r..4r+3}, o in {c, c+8, c+16, c+24}
    const int r = t >> 3;   // 0..7
    const int c = t & 7;    // 0..7

    int swx[4];
    #pragma unroll
    for (int i = 0; i < 4; i++) swx[i] = sw_x(4 * r + i);

    unsigned long long acc[4][4];
    #pragma unroll
    for (int i = 0; i < 4; i++)
        #pragma unroll
        for (int jo = 0; jo < 4; jo++)
            acc[i][jo] = 0ULL;

    // ---- main GEMM: pairs packed along k; all LDS conflict-free ----
    #pragma unroll 8
    for (int k4 = 0; k4 < IN_PLANES / 4; k4++) {
        unsigned long long xk0[4], xk1[4], wk0[4], wk1[4];
        #pragma unroll
        for (int i = 0; i < 4; i++) {
            double2 d = *reinterpret_cast<const double2*>(
                &xs[(4 * r + i) * IN_PLANES + ((k4 ^ swx[i]) << 2)]);
            xk0[i] = dal(d.x);
            xk1[i] = dal(d.y);
        }
        const int sw = ((k4 ^ c) << 2);   // same for all jo (o&7 == c)
        #pragma unroll
        for (int jo = 0; jo < 4; jo++) {
            double2 d = *reinterpret_cast<const double2*>(
                &wsT[(c + 8 * jo) * IN_PLANES + sw]);
            wk0[jo] = dal(d.x);
            wk1[jo] = dal(d.y);
        }
        #pragma unroll
        for (int i = 0; i < 4; i++)
            #pragma unroll
            for (int jo = 0; jo < 4; jo++) {
                FMA2(acc[i][jo], xk0[i], wk0[jo]);
                FMA2(acc[i][jo], xk1[i], wk1[jo]);
            }
    }

    // ---- epilogue: /128 + b0, exact-erf GELU, dot with w1, /32 + b1 ----
    const float inv_in = 1.0f / (float)IN_PLANES;
    const float inv_p  = 1.0f / (float)PLANES;

    float b0v[4], w1v[4];
    #pragma unroll
    for (int jo = 0; jo < 4; jo++) {
        int o = c + 8 * jo;
        b0v[jo] = b0[(size_t)v * PLANES + o];
        w1v[jo] = w1[(size_t)v * PLANES + o];
    }
    const float b1v = b1[v];

    float s[4];
    #pragma unroll
    for (int i = 0; i < 4; i++) {
        s[i] = 0.0f;
        #pragma unroll
        for (int jo = 0; jo < 4; jo++) {
            unsigned long long a = acc[i][jo];
            float lo = __uint_as_float((unsigned)(a & 0xffffffffULL));
            float hi = __uint_as_float((unsigned)(a >> 32));
            float h  = (lo + hi) * inv_in + b0v[jo];
            float g  = h * normcdff(h);          // exact-erf GELU
            s[i] += g * w1v[jo];
        }
    }

    #pragma unroll
    for (int i = 0; i < 4; i++) {
        s[i] += __shfl_xor_sync(0xffffffffu, s[i], 1);
        s[i] += __shfl_xor_sync(0xffffffffu, s[i], 2);
        s[i] += __shfl_xor_sync(0xffffffffu, s[i], 4);
    }

    if (c == 0) {
        #pragma unroll
        for (int i = 0; i < 4; i++) {
            int b = 4 * r + i;
            out[(size_t)b * n_sel + n] = s[i] * inv_p + b1v;
        }
    }
}

extern "C" void kernel_launch(void* const* d_in, const int* in_sizes, int n_in,
                              void* d_out, int out_size) {
    const float* x    = (const float*)d_in[0];
    const int*   vidx = (const int*)  d_in[1];
    const float* w0   = (const float*)d_in[2];
    const float* b0   = (const float*)d_in[3];
    const float* w1   = (const float*)d_in[4];
    const float* b1   = (const float*)d_in[5];
    float*       out  = (float*)d_out;

    const int n_sel = in_sizes[1];
    voxel_mlp_kernel<<<n_sel, 64>>>(x, vidx, w0, b0, w1, b1, out, n_sel);
}

// round 4
// speedup vs baseline: 1.0953x; 1.0953x over previous
#include <cuda_runtime.h>
#include <cstdint>

#define B_DIM 32
#define IN_PLANES 128
#define PLANES 32

#define XS_PITCH 132
#define WT_PITCH 132
// xs row base in floats: quad index = (b + 3*(b>>2)) mod 32 = 7r+i for b=4r+i -> distinct over r
#define XROW(b) ((b) * XS_PITCH + ((b) >> 2) * 12)
#define XS_SIZE (31 * XS_PITCH + 7 * 12 + IN_PLANES)   // 4304 floats
#define WT_SIZE (31 * WT_PITCH + IN_PLANES)            // 4220 floats
#define PER_VOX (XS_SIZE + WT_SIZE)                    // 8524 floats = 34096 B

// packed f32x2 FMA: lo += x.lo*w.lo ; hi += x.hi*w.hi (full fp32, 2x FFMA rate)
#define FMA2(a, xx, ww) asm("fma.rn.f32x2 %0, %1, %2, %0;" : "+l"(a) : "l"(xx), "l"(ww))

static __device__ __forceinline__ unsigned long long dal(double d) {
    return __double_as_longlong(d);
}

extern __shared__ float smem_dyn[];

__global__ __launch_bounds__(128) void voxel_mlp_kernel(
    const float* __restrict__ x,        // [B, n_sel, 128]
    const int*   __restrict__ vidx,     // [n_sel]
    const float* __restrict__ w0,       // [n_vox, 128, 32]
    const float* __restrict__ b0,       // [n_vox, 32]
    const float* __restrict__ w1,       // [n_vox, 32] (last dim 1)
    const float* __restrict__ b1,       // [n_vox]
    float*       __restrict__ out,      // [B, n_sel]
    int n_sel)
{
    const int t    = threadIdx.x;
    const int half = t >> 6;            // 0: warps 0-1, 1: warps 2-3
    const int tl   = t & 63;

    const int n = blockIdx.x * 2 + half;
    if (n >= n_sel) return;             // (n_sel even in practice; safe anyway)

    float* xs  = smem_dyn + half * PER_VOX;   // padded-pitch x rows
    float* wsT = xs + XS_SIZE;                // transposed w0, pitch 132

    const int v = vidx[n];
    const float* xg = x  + (size_t)n * IN_PLANES;
    const float* wg = w0 + (size_t)v * (IN_PLANES * PLANES);

    // ---- load x: coalesced LDG.128 -> STS.128, conflict-free (quads lane-consecutive) ----
    #pragma unroll
    for (int m = 0; m < 16; m++) {
        int j  = tl + 64 * m;
        int b  = j >> 5;        // warp-uniform row
        int c4 = j & 31;        // 16B chunk
        float4 val = *reinterpret_cast<const float4*>(xg + (size_t)b * n_sel * IN_PLANES + c4 * 4);
        *reinterpret_cast<float4*>(&xs[XROW(b) + c4 * 4]) = val;
    }

    // ---- load w0 [128][32]: register 4x4-block transpose into wsT[o][k], pitch 132 ----
    // store quad = (4*(l>>2) + (l&3) + const) mod 32 -> full lane permutation, conflict-free
    {
        const int l   = tl & 31;
        const int wrp = tl >> 5;        // 0..1 within this half
        const int o4  = l >> 2;
        #pragma unroll
        for (int it = 0; it < 4; it++) {
            const int k0 = ((l & 3) << 2) + (wrp << 4) + (it << 5);
            float4 f0 = *reinterpret_cast<const float4*>(wg + (k0 + 0) * PLANES + o4 * 4);
            float4 f1 = *reinterpret_cast<const float4*>(wg + (k0 + 1) * PLANES + o4 * 4);
            float4 f2 = *reinterpret_cast<const float4*>(wg + (k0 + 2) * PLANES + o4 * 4);
            float4 f3 = *reinterpret_cast<const float4*>(wg + (k0 + 3) * PLANES + o4 * 4);
            float4 t0 = make_float4(f0.x, f1.x, f2.x, f3.x);
            float4 t1 = make_float4(f0.y, f1.y, f2.y, f3.y);
            float4 t2 = make_float4(f0.z, f1.z, f2.z, f3.z);
            float4 t3 = make_float4(f0.w, f1.w, f2.w, f3.w);
            *reinterpret_cast<float4*>(&wsT[(4 * o4 + 0) * WT_PITCH + k0]) = t0;
            *reinterpret_cast<float4*>(&wsT[(4 * o4 + 1) * WT_PITCH + k0]) = t1;
            *reinterpret_cast<float4*>(&wsT[(4 * o4 + 2) * WT_PITCH + k0]) = t2;
            *reinterpret_cast<float4*>(&wsT[(4 * o4 + 3) * WT_PITCH + k0]) = t3;
        }
    }

    // per-half barrier: warps of this voxel only (id 1 or 2, 64 threads)
    asm volatile("bar.sync %0, %1;" :: "r"(half + 1), "r"(64) : "memory");

    // thread tile: b in {4r..4r+3}, o in {c, c+8, c+16, c+24}
    const int r = tl >> 3;   // 0..7
    const int c = tl & 7;    // 0..7

    const float* xb[4];
    const float* wb[4];
    #pragma unroll
    for (int i = 0; i < 4; i++)  xb[i]  = xs  + XROW(4 * r + i);
    #pragma unroll
    for (int jo = 0; jo < 4; jo++) wb[jo] = wsT + (c + 8 * jo) * WT_PITCH;

    unsigned long long acc[4][4];
    #pragma unroll
    for (int i = 0; i < 4; i++)
        #pragma unroll
        for (int jo = 0; jo < 4; jo++)
            acc[i][jo] = 0ULL;

    // ---- main GEMM: pairs packed along k; all addresses base + k4*16B (immediate offsets) ----
    #pragma unroll 8
    for (int k4 = 0; k4 < IN_PLANES / 4; k4++) {
        unsigned long long xk0[4], xk1[4], wk0[4], wk1[4];
        #pragma unroll
        for (int i = 0; i < 4; i++) {
            double2 d = *reinterpret_cast<const double2*>(xb[i] + k4 * 4);
            xk0[i] = dal(d.x);
            xk1[i] = dal(d.y);
        }
        #pragma unroll
        for (int jo = 0; jo < 4; jo++) {
            double2 d = *reinterpret_cast<const double2*>(wb[jo] + k4 * 4);
            wk0[jo] = dal(d.x);
            wk1[jo] = dal(d.y);
        }
        #pragma unroll
        for (int i = 0; i < 4; i++)
            #pragma unroll
            for (int jo = 0; jo < 4; jo++) {
                FMA2(acc[i][jo], xk0[i], wk0[jo]);
                FMA2(acc[i][jo], xk1[i], wk1[jo]);
            }
    }

    // ---- epilogue: /128 + b0, exact-erf GELU, dot w1, /32 + b1 ----
    const float inv_in = 1.0f / (float)IN_PLANES;
    const float inv_p  = 1.0f / (float)PLANES;

    float b0v[4], w1v[4];
    #pragma unroll
    for (int jo = 0; jo < 4; jo++) {
        int o = c + 8 * jo;
        b0v[jo] = b0[(size_t)v * PLANES + o];
        w1v[jo] = w1[(size_t)v * PLANES + o];
    }
    const float b1v = b1[v];

    float s[4];
    #pragma unroll
    for (int i = 0; i < 4; i++) {
        s[i] = 0.0f;
        #pragma unroll
        for (int jo = 0; jo < 4; jo++) {
            unsigned long long a = acc[i][jo];
            float lo = __uint_as_float((unsigned)(a & 0xffffffffULL));
            float hi = __uint_as_float((unsigned)(a >> 32));
            float h  = (lo + hi) * inv_in + b0v[jo];
            float g  = h * normcdff(h);          // exact-erf GELU
            s[i] += g * w1v[jo];
        }
    }

    #pragma unroll
    for (int i = 0; i < 4; i++) {
        s[i] += __shfl_xor_sync(0xffffffffu, s[i], 1);
        s[i] += __shfl_xor_sync(0xffffffffu, s[i], 2);
        s[i] += __shfl_xor_sync(0xffffffffu, s[i], 4);
    }

    if (c == 0) {
        #pragma unroll
        for (int i = 0; i < 4; i++) {
            int b = 4 * r + i;
            out[(size_t)b * n_sel + n] = s[i] * inv_p + b1v;
        }
    }
}

extern "C" void kernel_launch(void* const* d_in, const int* in_sizes, int n_in,
                              void* d_out, int out_size) {
    const float* x    = (const float*)d_in[0];
    const int*   vidx = (const int*)  d_in[1];
    const float* w0   = (const float*)d_in[2];
    const float* b0   = (const float*)d_in[3];
    const float* w1   = (const float*)d_in[4];
    const float* b1   = (const float*)d_in[5];
    float*       out  = (float*)d_out;

    const int n_sel = in_sizes[1];
    const int smem_bytes = 2 * PER_VOX * (int)sizeof(float);   // 68192 B

    static int configured = -1;
    if (configured != smem_bytes) {
        cudaFuncSetAttribute(voxel_mlp_kernel,
                             cudaFuncAttributeMaxDynamicSharedMemorySize, smem_bytes);
        configured = smem_bytes;
    }

    const int grid = (n_sel + 1) / 2;
    voxel_mlp_kernel<<<grid, 128, smem_bytes>>>(x, vidx, w0, b0, w1, b1, out, n_sel);
}